// round 1
// baseline (speedup 1.0000x reference)
#include <cuda_runtime.h>

// Scratch for x3 [512 rows x 55 probs], padded to stride 64.
static __device__ float g_x3[512 * 64];

// ---------------------------------------------------------------------------
// Kernel A: tiny MLP head.
//   h = leakyrelu(x @ w2^T + b2)   [512,256]
//   z = h @ w3^T + b3              [512,55]
//   x3 = [softmax(z[:, :5]) , softmax over 5 digit-groups of 10]
// One block handles 4 batch rows. 256 threads.
// ---------------------------------------------------------------------------
__global__ void __launch_bounds__(256) mlp_head_kernel(
    const float* __restrict__ x,
    const float* __restrict__ w2,
    const float* __restrict__ b2,
    const float* __restrict__ w3,
    const float* __restrict__ b3)
{
    __shared__ float xs[4 * 512];   // 4 rows of x
    __shared__ float hs[4 * 256];   // 4 rows of h
    __shared__ float zs[4][60];     // 4 rows of z (55 used)

    const int t  = threadIdx.x;
    const int r0 = blockIdx.x * 4;  // first batch row of this block

    // --- load 4 rows of x into smem (coalesced float4) ---
    {
        const float4* xg  = reinterpret_cast<const float4*>(x + (size_t)r0 * 512);
        float4*       xsv = reinterpret_cast<float4*>(xs);
        for (int idx = t; idx < 512; idx += 256) xsv[idx] = xg[idx];
    }
    __syncthreads();

    // --- GEMM1: thread t owns hidden unit j=t for all 4 rows ---
    {
        float a0 = 0.f, a1 = 0.f, a2 = 0.f, a3 = 0.f;
        const float4* wr  = reinterpret_cast<const float4*>(w2 + (size_t)t * 512);
        const float4* x0p = reinterpret_cast<const float4*>(xs);
        const float4* x1p = reinterpret_cast<const float4*>(xs + 512);
        const float4* x2p = reinterpret_cast<const float4*>(xs + 1024);
        const float4* x3p = reinterpret_cast<const float4*>(xs + 1536);
        #pragma unroll 4
        for (int k = 0; k < 128; ++k) {
            const float4 w = wr[k];
            float4 v;
            v = x0p[k];
            a0 = fmaf(w.x, v.x, a0); a0 = fmaf(w.y, v.y, a0);
            a0 = fmaf(w.z, v.z, a0); a0 = fmaf(w.w, v.w, a0);
            v = x1p[k];
            a1 = fmaf(w.x, v.x, a1); a1 = fmaf(w.y, v.y, a1);
            a1 = fmaf(w.z, v.z, a1); a1 = fmaf(w.w, v.w, a1);
            v = x2p[k];
            a2 = fmaf(w.x, v.x, a2); a2 = fmaf(w.y, v.y, a2);
            a2 = fmaf(w.z, v.z, a2); a2 = fmaf(w.w, v.w, a2);
            v = x3p[k];
            a3 = fmaf(w.x, v.x, a3); a3 = fmaf(w.y, v.y, a3);
            a3 = fmaf(w.z, v.z, a3); a3 = fmaf(w.w, v.w, a3);
        }
        const float bb = b2[t];
        a0 += bb; a1 += bb; a2 += bb; a3 += bb;
        hs[0 * 256 + t] = (a0 >= 0.f) ? a0 : 0.01f * a0;
        hs[1 * 256 + t] = (a1 >= 0.f) ? a1 : 0.01f * a1;
        hs[2 * 256 + t] = (a2 >= 0.f) ? a2 : 0.01f * a2;
        hs[3 * 256 + t] = (a3 >= 0.f) ? a3 : 0.01f * a3;
    }
    __syncthreads();

    // --- GEMM2: 4 rows x 55 outputs = 220 threads, one z element each ---
    if (t < 220) {
        const int r = t / 55;
        const int c = t - 55 * r;
        const float4* hv = reinterpret_cast<const float4*>(hs + r * 256);
        const float4* wv = reinterpret_cast<const float4*>(w3 + (size_t)c * 256);
        float acc = 0.f;
        #pragma unroll 8
        for (int k = 0; k < 64; ++k) {
            const float4 a = hv[k];
            const float4 w = wv[k];
            acc = fmaf(a.x, w.x, acc); acc = fmaf(a.y, w.y, acc);
            acc = fmaf(a.z, w.z, acc); acc = fmaf(a.w, w.w, acc);
        }
        zs[r][c] = acc + b3[c];
    }
    __syncthreads();

    // --- softmaxes: 4 rows x 6 groups = 24 threads, serial per group ---
    if (t < 24) {
        const int r     = t / 6;
        const int g     = t - 6 * r;
        const int start = (g == 0) ? 0 : 5 + 10 * (g - 1);
        const int len   = (g == 0) ? 5 : 10;
        float m = -3.0e38f;
        for (int c = 0; c < len; ++c) m = fmaxf(m, zs[r][start + c]);
        float s = 0.f;
        for (int c = 0; c < len; ++c) s += __expf(zs[r][start + c] - m);
        const float inv = 1.0f / s;
        float* dst = &g_x3[(size_t)(r0 + r) * 64];
        for (int c = 0; c < len; ++c)
            dst[start + c] = __expf(zs[r][start + c] - m) * inv;
    }
}

// ---------------------------------------------------------------------------
// Kernel B: expansion. out[b, i] for i in [0, 99999).
//
// Structure of the reference (ndig = #thresholds passed, last digit dropped):
//   i == 0        -> p[1]*p[5]
//   i in [1,10)   -> p[0]
//   i >= 10       -> value depends only on r = i/10:
//     r in [1,10)      : p[1]*p[5+r]
//     r in [10,100)    : p[2]*p[5+d1]*p[15+d2]
//     r in [100,1000)  : p[3]*p[5+d1]*p[15+d2]*p[25+d3]
//     r in [1000,10000): p[4]*p[5+d1]*p[15+d2]*p[25+d3]*p[35+d4]
//   (d1..d4 = decimal digits of r, msd first)
//
// Each block: 256 run-values into smem, then 2560 coalesced stores.
// grid = (40, 512), block = 256.
// ---------------------------------------------------------------------------
__global__ void __launch_bounds__(256) expand_kernel(float* __restrict__ out)
{
    __shared__ float p[64];
    __shared__ float sv[256];

    const unsigned t = threadIdx.x;
    const unsigned b = blockIdx.y;

    if (t < 64) p[t] = g_x3[(size_t)b * 64 + t];
    __syncthreads();

    // --- phase 1: one run-value per thread ---
    const unsigned r = blockIdx.x * 256u + t;
    float v = 0.f;
    if (r < 10000u) {
        if (r == 0u) {
            v = p[0];                       // elements 1..9; element 0 patched below
        } else if (r < 10u) {
            v = p[1] * p[5 + r];
        } else if (r < 100u) {
            const unsigned q1 = r / 10u;
            v = p[2] * p[5 + q1] * p[15 + (r - 10u * q1)];
        } else if (r < 1000u) {
            const unsigned q1 = r / 10u, q2 = r / 100u;
            v = p[3] * p[5 + q2] * p[15 + (q1 - 10u * q2)] * p[25 + (r - 10u * q1)];
        } else {
            const unsigned q1 = r / 10u, q2 = r / 100u, q3 = r / 1000u;
            v = p[4] * p[5 + q3] * p[15 + (q2 - 10u * q3)]
                     * p[25 + (q1 - 10u * q2)] * p[35 + (r - 10u * q1)];
        }
    }
    sv[t] = v;
    __syncthreads();

    // --- phase 2: coalesced expansion, 2560 elements per block ---
    float* o = out + (size_t)b * 99999u;
    const unsigned base = blockIdx.x * 2560u;
    #pragma unroll
    for (unsigned it = 0; it < 10u; ++it) {
        const unsigned off = it * 256u + t;      // local offset in [0, 2560)
        const unsigned idx = base + off;         // element index within row
        if (idx < 99999u) {
            o[idx] = sv[off / 10u];
        }
    }
    // patch the single special element out[b, 0]
    if (blockIdx.x == 0 && t == 0) {
        o[0] = p[1] * p[5];
    }
}

// ---------------------------------------------------------------------------
extern "C" void kernel_launch(void* const* d_in, const int* in_sizes, int n_in,
                              void* d_out, int out_size)
{
    (void)in_sizes; (void)n_in; (void)out_size;
    const float* x  = (const float*)d_in[0];   // [512, 512]
    const float* w2 = (const float*)d_in[1];   // [256, 512]
    const float* b2 = (const float*)d_in[2];   // [256]
    const float* w3 = (const float*)d_in[3];   // [55, 256]
    const float* b3 = (const float*)d_in[4];   // [55]
    float* out = (float*)d_out;                // [512, 99999]

    mlp_head_kernel<<<128, 256>>>(x, w2, b2, w3, b3);
    expand_kernel<<<dim3(40, 512), 256>>>(out);
}

// round 2
// speedup vs baseline: 1.1307x; 1.1307x over previous
#include <cuda_runtime.h>

// Scratch: split-K partials [4][512*256] and x3 [512 x 64].
static __device__ float g_part[4][512 * 256];
static __device__ float g_x3[512 * 64];

// ---------------------------------------------------------------------------
// Kernel A1: split-K partial GEMM.  part[z] += x[64r x 128k] @ w2^T[128k x 64h]
// grid (8 rowTiles, 4 hidTiles, 4 kSplits), 256 threads, 4x4 register tiles.
// ---------------------------------------------------------------------------
__global__ void __launch_bounds__(256) gemm1_part_kernel(
    const float* __restrict__ x,    // [512, 512]
    const float* __restrict__ w2)   // [256, 512]
{
    __shared__ float xs[64][68];
    __shared__ float ws[64][68];

    const int t  = threadIdx.x;
    const int r0 = blockIdx.x * 64;
    const int h0 = blockIdx.y * 64;
    const int k0 = blockIdx.z * 128;
    const int tx = t & 15;          // col group
    const int ty = t >> 4;          // row group

    float acc[4][4];
    #pragma unroll
    for (int i = 0; i < 4; ++i)
        #pragma unroll
        for (int j = 0; j < 4; ++j) acc[i][j] = 0.f;

    for (int kc = 0; kc < 2; ++kc) {
        const int ko = k0 + kc * 64;
        __syncthreads();
        // cooperative coalesced load: 64 rows x 64 k (16 float4 per row)
        #pragma unroll
        for (int i = 0; i < 4; ++i) {
            const int idx = t + i * 256;
            const int r  = idx >> 4;
            const int kq = idx & 15;
            float4 vx = *reinterpret_cast<const float4*>(
                x + (size_t)(r0 + r) * 512 + ko + kq * 4);
            *reinterpret_cast<float4*>(&xs[r][kq * 4]) = vx;
            float4 vw = *reinterpret_cast<const float4*>(
                w2 + (size_t)(h0 + r) * 512 + ko + kq * 4);
            *reinterpret_cast<float4*>(&ws[r][kq * 4]) = vw;
        }
        __syncthreads();

        #pragma unroll 4
        for (int kq = 0; kq < 64; kq += 4) {
            float4 a[4], bv[4];
            #pragma unroll
            for (int i = 0; i < 4; ++i)
                a[i] = *reinterpret_cast<const float4*>(&xs[ty * 4 + i][kq]);
            #pragma unroll
            for (int j = 0; j < 4; ++j)
                bv[j] = *reinterpret_cast<const float4*>(&ws[tx * 4 + j][kq]);
            #pragma unroll
            for (int i = 0; i < 4; ++i)
                #pragma unroll
                for (int j = 0; j < 4; ++j) {
                    acc[i][j] = fmaf(a[i].x, bv[j].x, acc[i][j]);
                    acc[i][j] = fmaf(a[i].y, bv[j].y, acc[i][j]);
                    acc[i][j] = fmaf(a[i].z, bv[j].z, acc[i][j]);
                    acc[i][j] = fmaf(a[i].w, bv[j].w, acc[i][j]);
                }
        }
    }

    // store partials (float4 per row of the 4x4 tile)
    float* dst = g_part[blockIdx.z];
    #pragma unroll
    for (int i = 0; i < 4; ++i) {
        float4 v = make_float4(acc[i][0], acc[i][1], acc[i][2], acc[i][3]);
        *reinterpret_cast<float4*>(
            dst + (size_t)(r0 + ty * 4 + i) * 256 + h0 + tx * 4) = v;
    }
}

// ---------------------------------------------------------------------------
// Kernel A2: reduce partials + bias + LeakyReLU, then GEMM2 + softmaxes -> x3.
// One block per 8 batch rows, 256 threads, grid 64.
// ---------------------------------------------------------------------------
__global__ void __launch_bounds__(256) head_kernel(
    const float* __restrict__ b2,   // [256]
    const float* __restrict__ w3,   // [55, 256]
    const float* __restrict__ b3)   // [55]
{
    __shared__ float hs[8][256];
    __shared__ float zs[8][60];

    const int t  = threadIdx.x;
    const int r0 = blockIdx.x * 8;

    // h = leakyrelu(sum_z part[z] + b2)
    const float bb = b2[t];
    #pragma unroll
    for (int i = 0; i < 8; ++i) {
        const size_t off = (size_t)(r0 + i) * 256 + t;
        float s = bb + g_part[0][off] + g_part[1][off]
                     + g_part[2][off] + g_part[3][off];
        hs[i][t] = (s >= 0.f) ? s : 0.01f * s;
    }
    __syncthreads();

    // z = h @ w3^T + b3 : 8*55 = 440 dots of length 256
    for (int o = t; o < 440; o += 256) {
        const int r = o / 55;
        const int c = o - 55 * r;
        const float4* hv = reinterpret_cast<const float4*>(hs[r]);
        const float4* wv = reinterpret_cast<const float4*>(w3 + (size_t)c * 256);
        float acc = 0.f;
        #pragma unroll 8
        for (int k = 0; k < 64; ++k) {
            const float4 a = hv[k];
            const float4 w = __ldg(&wv[k]);
            acc = fmaf(a.x, w.x, acc); acc = fmaf(a.y, w.y, acc);
            acc = fmaf(a.z, w.z, acc); acc = fmaf(a.w, w.w, acc);
        }
        zs[r][c] = acc + b3[c];
    }
    __syncthreads();

    // softmaxes: 8 rows x 6 groups
    if (t < 48) {
        const int r     = t / 6;
        const int g     = t - 6 * r;
        const int start = (g == 0) ? 0 : 5 + 10 * (g - 1);
        const int len   = (g == 0) ? 5 : 10;
        float m = -3.0e38f;
        for (int c = 0; c < len; ++c) m = fmaxf(m, zs[r][start + c]);
        float s = 0.f;
        for (int c = 0; c < len; ++c) s += __expf(zs[r][start + c] - m);
        const float inv = 1.0f / s;
        float* dst = &g_x3[(size_t)(r0 + r) * 64];
        for (int c = 0; c < len; ++c)
            dst[start + c] = __expf(zs[r][start + c] - m) * inv;
    }
}

// ---------------------------------------------------------------------------
// Kernel B: expansion, vectorized.  out[b, i], i in [0, 99999).
// out[b,i] is constant over runs of 10 (r = i/10); specials: i=0, r=0.
// Block = (bx, b): floats [bx*10240, min(+10240, 99999)) of row b.
// Phase 1: 1025 run values into smem.  Phase 2: aligned float4 stores.
// ---------------------------------------------------------------------------
__global__ void __launch_bounds__(256) expand_kernel(float* __restrict__ out)
{
    __shared__ float p[64];
    __shared__ float sv[1025 + 7];

    const unsigned t  = threadIdx.x;
    const unsigned bx = blockIdx.x;
    const unsigned b  = blockIdx.y;

    if (t < 64) p[t] = g_x3[(size_t)b * 64 + t];
    __syncthreads();

    const unsigned rbase = bx * 1024u;

    // --- phase 1: run values (need one extra for boundary crossing) ---
    for (unsigned ri = t; ri < 1025u; ri += 256u) {
        const unsigned r = rbase + ri;
        float v = 0.f;
        if (r < 10000u) {
            if (r == 0u) {
                v = p[0];                       // i in [1,10); i=0 patched below
            } else if (r < 10u) {
                v = p[1] * p[5 + r];
            } else if (r < 100u) {
                const unsigned q1 = r / 10u;
                v = p[2] * p[5 + q1] * p[15 + (r - 10u * q1)];
            } else if (r < 1000u) {
                const unsigned q1 = r / 10u, q2 = r / 100u;
                v = p[3] * p[5 + q2] * p[15 + (q1 - 10u * q2)]
                         * p[25 + (r - 10u * q1)];
            } else {
                const unsigned q1 = r / 10u, q2 = r / 100u, q3 = r / 1000u;
                v = p[4] * p[5 + q3] * p[15 + (q2 - 10u * q3)]
                         * p[25 + (q1 - 10u * q2)] * p[35 + (r - 10u * q1)];
            }
        }
        sv[ri] = v;
    }
    __syncthreads();

    // --- phase 2: stores ---
    float* o = out + (size_t)b * 99999u;
    const unsigned s0 = bx * 10240u;
    const unsigned s1 = (s0 + 10240u < 99999u) ? (s0 + 10240u) : 99999u;

    const unsigned abs0 = b * 99999u + s0;             // absolute float index
    const unsigned pad  = (4u - (abs0 & 3u)) & 3u;     // scalar head length

    // scalar head
    if (t < pad && s0 + t < s1) {
        const unsigned i = s0 + t;
        o[i] = sv[i / 10u - rbase];
    }

    // vector body
    const unsigned vstart = s0 + pad;
    const unsigned nv = (s1 > vstart) ? ((s1 - vstart) >> 2) : 0u;
    float4* ov = reinterpret_cast<float4*>(o + vstart);
    for (unsigned v = t; v < nv; v += 256u) {
        const unsigned i   = vstart + 4u * v;
        const unsigned r   = i / 10u;
        const unsigned rem = i - 10u * r;
        const unsigned ri  = r - rbase;
        const float f0 = sv[ri];
        const float f1 = sv[ri + 1u];
        float4 w;
        w.x = f0;
        w.y = (rem + 1u < 10u) ? f0 : f1;
        w.z = (rem + 2u < 10u) ? f0 : f1;
        w.w = (rem + 3u < 10u) ? f0 : f1;
        ov[v] = w;
    }

    // scalar tail
    const unsigned tstart = vstart + nv * 4u;
    if (t < s1 - tstart) {
        const unsigned i = tstart + t;
        o[i] = sv[i / 10u - rbase];
    }

    // patch out[b, 0]
    if (bx == 0u) {
        __syncthreads();
        if (t == 0u) o[0] = p[1] * p[5];
    }
}

// ---------------------------------------------------------------------------
extern "C" void kernel_launch(void* const* d_in, const int* in_sizes, int n_in,
                              void* d_out, int out_size)
{
    (void)in_sizes; (void)n_in; (void)out_size;
    const float* x  = (const float*)d_in[0];   // [512, 512]
    const float* w2 = (const float*)d_in[1];   // [256, 512]
    const float* b2 = (const float*)d_in[2];   // [256]
    const float* w3 = (const float*)d_in[3];   // [55, 256]
    const float* b3 = (const float*)d_in[4];   // [55]
    float* out = (float*)d_out;                // [512, 99999]

    gemm1_part_kernel<<<dim3(8, 4, 4), 256>>>(x, w2);
    head_kernel<<<64, 256>>>(b2, w3, b3);
    expand_kernel<<<dim3(10, 512), 256>>>(out);
}